// round 14
// baseline (speedup 1.0000x reference)
#include <cuda_runtime.h>
#include <cuda_fp16.h>
#include <cstdint>

#define THREADS 512

// ---- SMEM byte offsets ----
enum {
  O_FWA  = 0,        // GEMM1 B frags: uint2[16 nblk][4 kt][32 lane] (16 KB)
  O_FWNH = 16384,    // GEMM2 B frags: uint2[32 nblk][4 kt][32 lane] (32 KB)
  O_FWO  = 49152,    // GEMM3 B frags: uint2[8 nblk][8 kt][32 lane]  (16 KB)
  O_HH   = 65536,    // H hi [64][136] half
  O_HL   = 82944,
  O_AS   = 100352,   // A f32 [64][132]
  O_BA   = 134144,   // f32[128]
  O_BN   = 134656,
  O_BH   = 135168,
  O_BO   = 135680,   // f32[64]
  O_MSK  = 135936,   // f32[256]
  SMEM_TOTAL = 136960
};

#define LD_H   136
#define LD_AS  132

// K-permutation: MMA slot pair (2q,2q+1) holds actual k = (4q,4q+1),
// slot pair (2q+8,2q+9) holds actual k = (4q+2,4q+3), within each 16-k tile.
// A-side: one contiguous float4/lane per k-tile. B-side: pack consecutive
// k0..k0+3 per lane. Memory layouts (A_s, H, out) stay in ACTUAL order.

__device__ __forceinline__ void mma_f16(float* c, const uint32_t* a,
                                        uint32_t b0, uint32_t b1) {
    asm volatile(
        "mma.sync.aligned.m16n8k16.row.col.f32.f16.f16.f32 "
        "{%0,%1,%2,%3}, {%4,%5,%6,%7}, {%8,%9}, {%0,%1,%2,%3};\n"
        : "+f"(c[0]), "+f"(c[1]), "+f"(c[2]), "+f"(c[3])
        : "r"(a[0]), "r"(a[1]), "r"(a[2]), "r"(a[3]), "r"(b0), "r"(b1));
}

__device__ __forceinline__ void sp2(float2 v, uint32_t& h, uint32_t& l) {
    __half2 hh = __floats2half2_rn(v.x, v.y);
    __half2 ll = __floats2half2_rn(v.x - __low2float(hh), v.y - __high2float(hh));
    h = *reinterpret_cast<uint32_t*>(&hh);
    l = *reinterpret_cast<uint32_t*>(&ll);
}

__device__ __forceinline__ float relu(float x) { return fmaxf(x, 0.f); }

// round 4 consecutive-k weight values to fp16 packed as uint2 (b0 = k0,k0+1; b1 = k0+2,k0+3)
__device__ __forceinline__ uint2 packB(float w0, float w1, float w2, float w3) {
    __half2 h01 = __floats2half2_rn(w0, w1);
    __half2 h23 = __floats2half2_rn(w2, w3);
    uint2 r;
    r.x = *reinterpret_cast<uint32_t*>(&h01);
    r.y = *reinterpret_cast<uint32_t*>(&h23);
    return r;
}

// fp16 hi/lo A-fragments (permuted-K): one float4 per lane per row per k-tile
__device__ __forceinline__ void load_afrags(const float* rl, const float* rh,
                                            int q, uint32_t ah[4][4], uint32_t al[4][4]) {
#pragma unroll
    for (int kt = 0; kt < 4; ++kt) {
        float4 v0 = *reinterpret_cast<const float4*>(rl + 16 * kt + 4 * q);
        float4 v1 = *reinterpret_cast<const float4*>(rh + 16 * kt + 4 * q);
        sp2(make_float2(v0.x, v0.y), ah[kt][0], al[kt][0]);
        sp2(make_float2(v1.x, v1.y), ah[kt][1], al[kt][1]);
        sp2(make_float2(v0.z, v0.w), ah[kt][2], al[kt][2]);
        sp2(make_float2(v1.z, v1.w), ah[kt][3], al[kt][3]);
    }
}

__global__ __launch_bounds__(THREADS, 1)
void gat_mma10(const float* __restrict__ agent,
               const float* __restrict__ neighbor,
               const int*   __restrict__ nmask,
               const float* __restrict__ Wa, const float* __restrict__ ba,
               const float* __restrict__ Wn, const float* __restrict__ bn,
               const float* __restrict__ Wh, const float* __restrict__ bh,
               const float* __restrict__ Wo, const float* __restrict__ bo,
               float* __restrict__ out, int n, int ntiles)
{
    extern __shared__ char sm[];
    uint2*  fWA  = (uint2*)(sm + O_FWA);
    uint2*  fWNH = (uint2*)(sm + O_FWNH);
    uint2*  fWO  = (uint2*)(sm + O_FWO);
    __half* Hh   = (__half*)(sm + O_HH);
    __half* Hl   = (__half*)(sm + O_HL);
    float*  A_s  = (float*)(sm + O_AS);
    float*  sba  = (float*)(sm + O_BA);
    float*  sbn  = (float*)(sm + O_BN);
    float*  sbh  = (float*)(sm + O_BH);
    float*  sbo  = (float*)(sm + O_BO);
    float*  msk  = (float*)(sm + O_MSK);

    const int tid  = threadIdx.x;
    const int lane = tid & 31;
    const int w    = tid >> 5;
    const int g    = lane >> 2;
    const int q    = lane & 3;

    // ---- once: pack rounded-fp16 weights (permuted-K: consecutive k per lane) ----
    for (int i = tid; i < 2048; i += THREADS) {          // Wa^T: 16 nblk x 4 kt
        int li = i & 31, kt = (i >> 5) & 3, nb = i >> 7;
        int nn = nb * 8 + (li >> 2), k0 = kt * 16 + 4 * (li & 3);
        fWA[i] = packB(Wa[k0 * 128 + nn], Wa[(k0 + 1) * 128 + nn],
                       Wa[(k0 + 2) * 128 + nn], Wa[(k0 + 3) * 128 + nn]);
    }
    for (int i = tid; i < 4096; i += THREADS) {          // (Wn|Wh)^T: 32 nblk x 4 kt
        int li = i & 31, kt = (i >> 5) & 3, nb = i >> 7;
        int nn = nb * 8 + (li >> 2), k0 = kt * 16 + 4 * (li & 3);
        const float* Wsrc = (nn < 128) ? Wn : Wh;
        int nc = (nn < 128) ? nn : nn - 128;
        fWNH[i] = packB(Wsrc[k0 * 128 + nc], Wsrc[(k0 + 1) * 128 + nc],
                        Wsrc[(k0 + 2) * 128 + nc], Wsrc[(k0 + 3) * 128 + nc]);
    }
    for (int i = tid; i < 2048; i += THREADS) {          // Wo^T: 8 nblk x 8 kt
        int li = i & 31, kt = (i >> 5) & 7, nb = i >> 8;
        int nn = nb * 8 + (li >> 2), k0 = kt * 16 + 4 * (li & 3);
        fWO[i] = packB(Wo[k0 * 64 + nn], Wo[(k0 + 1) * 64 + nn],
                       Wo[(k0 + 2) * 64 + nn], Wo[(k0 + 3) * 64 + nn]);
    }
    if (tid < 128) {
        sba[tid] = ba[tid]; sbn[tid] = bn[tid]; sbh[tid] = bh[tid];
        if (tid < 64) sbo[tid] = bo[tid];
    }
    __syncthreads();

    for (int tile = blockIdx.x; tile < ntiles; tile += gridDim.x) {
        const int base = tile * 64;

        if (tid < 256) {
            int ag = min(base + (tid >> 2), n - 1);
            msk[tid] = (float)nmask[(size_t)ag * 4 + (tid & 3)];
        }

        // ---- GEMM1: A_s = relu(X @ Wa + ba)  [64 x 128], K=64 ----
        {
            const int rb = w & 3, cs = w >> 2;
            uint32_t ah[4][4], al[4][4];
            int rlo = min(base + rb * 16 + g,     n - 1);
            int rhi = min(base + rb * 16 + g + 8, n - 1);
            load_afrags(agent + (size_t)rlo * 64, agent + (size_t)rhi * 64, q, ah, al);
#pragma unroll
            for (int nt = 0; nt < 4; ++nt) {
                float c[4] = {0.f, 0.f, 0.f, 0.f};
                const int nb = cs * 4 + nt;
#pragma unroll
                for (int kt = 0; kt < 4; ++kt) {
                    uint2 B = fWA[(nb * 4 + kt) * 32 + lane];
                    mma_f16(c, ah[kt], B.x, B.y);
                    mma_f16(c, al[kt], B.x, B.y);
                }
                int colc = cs * 32 + nt * 8 + 2 * q;
                float2 bav = *reinterpret_cast<const float2*>(sba + colc);
                float* d0 = A_s + (rb * 16 + g) * LD_AS + colc;
                float* d1 = A_s + (rb * 16 + g + 8) * LD_AS + colc;
                d0[0] = relu(c[0] + bav.x); d0[1] = relu(c[1] + bav.y);
                d1[0] = relu(c[2] + bav.x); d1[1] = relu(c[3] + bav.y);
            }
        }
        __syncthreads();

        // ---- GEMM2 + attention epilogue: one 16-row block per warp ----
        {
            const int blk  = w;                  // 4 agents
            const int a_lo = blk * 4 + (g >> 2);
            const int a_hi = a_lo + 2;
            int agl = min(base + a_lo, n - 1);
            int agh = min(base + a_hi, n - 1);
            uint32_t ah[4][4], al[4][4];
            load_afrags(neighbor + ((size_t)agl * 4 + (g & 3)) * 64,
                        neighbor + ((size_t)agh * 4 + (g & 3)) * 64, q, ah, al);

            const float mk_lo = msk[blk * 16 + g];
            const float mk_hi = msk[blk * 16 + g + 8];
            const float* arow_lo = A_s + a_lo * LD_AS;
            const float* arow_hi = A_s + a_hi * LD_AS;

#pragma unroll 1
            for (int h = 0; h < 4; ++h) {
                float c[4][4] = {};
                // --- nr GEMM (nblk = 4h+nt) ---
#pragma unroll
                for (int kt = 0; kt < 4; ++kt) {
#pragma unroll
                    for (int nt = 0; nt < 4; ++nt) {
                        uint2 B = fWNH[((4 * h + nt) * 4 + kt) * 32 + lane];
                        mma_f16(c[nt], ah[kt], B.x, B.y);
                        mma_f16(c[nt], al[kt], B.x, B.y);
                    }
                }
                // --- attention logits ---
                float p_lo = 0.f, p_hi = 0.f;
#pragma unroll
                for (int nt = 0; nt < 4; ++nt) {
                    int colc = 32 * h + 8 * nt + 2 * q;
                    float2 bnv = *reinterpret_cast<const float2*>(sbn + colc);
                    float e0 = relu(c[nt][0] + bnv.x), e1 = relu(c[nt][1] + bnv.y);
                    float e2 = relu(c[nt][2] + bnv.x), e3 = relu(c[nt][3] + bnv.y);
                    float2 avl = *reinterpret_cast<const float2*>(arow_lo + colc);
                    float2 avh = *reinterpret_cast<const float2*>(arow_hi + colc);
                    p_lo = fmaf(e0, avl.x, fmaf(e1, avl.y, p_lo));
                    p_hi = fmaf(e2, avh.x, fmaf(e3, avh.y, p_hi));
                }
                p_lo += __shfl_xor_sync(0xffffffffu, p_lo, 1);
                p_lo += __shfl_xor_sync(0xffffffffu, p_lo, 2);
                p_hi += __shfl_xor_sync(0xffffffffu, p_hi, 1);
                p_hi += __shfl_xor_sync(0xffffffffu, p_hi, 2);
                // --- softmax over the agent's 4 neighbor rows ---
                float lg_lo = fmaf(mk_lo, -1e8f, p_lo);
                float lg_hi = fmaf(mk_hi, -1e8f, p_hi);
                float m_lo = lg_lo, m_hi = lg_hi;
                m_lo = fmaxf(m_lo, __shfl_xor_sync(0xffffffffu, m_lo, 4));
                m_lo = fmaxf(m_lo, __shfl_xor_sync(0xffffffffu, m_lo, 8));
                m_hi = fmaxf(m_hi, __shfl_xor_sync(0xffffffffu, m_hi, 4));
                m_hi = fmaxf(m_hi, __shfl_xor_sync(0xffffffffu, m_hi, 8));
                float e_lo = __expf(lg_lo - m_lo), e_hi = __expf(lg_hi - m_hi);
                float s_lo = e_lo, s_hi = e_hi;
                s_lo += __shfl_xor_sync(0xffffffffu, s_lo, 4);
                s_lo += __shfl_xor_sync(0xffffffffu, s_lo, 8);
                s_hi += __shfl_xor_sync(0xffffffffu, s_hi, 4);
                s_hi += __shfl_xor_sync(0xffffffffu, s_hi, 8);
                float sc_lo = (1.f - mk_lo) * e_lo * 0.25f / s_lo;
                float sc_hi = (1.f - mk_hi) * e_hi * 0.25f / s_hi;

                // --- nh GEMM (nblk = 16+4h+nt) ---
#pragma unroll
                for (int nt = 0; nt < 4; ++nt)
                    c[nt][0] = c[nt][1] = c[nt][2] = c[nt][3] = 0.f;
#pragma unroll
                for (int kt = 0; kt < 4; ++kt) {
#pragma unroll
                    for (int nt = 0; nt < 4; ++nt) {
                        uint2 B = fWNH[((16 + 4 * h + nt) * 4 + kt) * 32 + lane];
                        mma_f16(c[nt], ah[kt], B.x, B.y);
                        mma_f16(c[nt], al[kt], B.x, B.y);
                    }
                }
                // --- weighted mean -> H (stored in ACTUAL col order) ---
#pragma unroll
                for (int nt = 0; nt < 4; ++nt) {
                    int colc = 32 * h + 8 * nt + 2 * q;
                    float2 bhv = *reinterpret_cast<const float2*>(sbh + colc);
                    float f0 = relu(c[nt][0] + bhv.x) * sc_lo;
                    float f1 = relu(c[nt][1] + bhv.y) * sc_lo;
                    float f2 = relu(c[nt][2] + bhv.x) * sc_hi;
                    float f3 = relu(c[nt][3] + bhv.y) * sc_hi;
                    f0 += __shfl_xor_sync(0xffffffffu, f0, 4);
                    f0 += __shfl_xor_sync(0xffffffffu, f0, 8);
                    f1 += __shfl_xor_sync(0xffffffffu, f1, 4);
                    f1 += __shfl_xor_sync(0xffffffffu, f1, 8);
                    f2 += __shfl_xor_sync(0xffffffffu, f2, 4);
                    f2 += __shfl_xor_sync(0xffffffffu, f2, 8);
                    f3 += __shfl_xor_sync(0xffffffffu, f3, 4);
                    f3 += __shfl_xor_sync(0xffffffffu, f3, 8);
                    if ((g & 3) == 0) {
                        uint32_t hp, lp;
                        sp2(make_float2(f0, f1), hp, lp);
                        *reinterpret_cast<uint32_t*>(Hh + a_lo * LD_H + colc) = hp;
                        *reinterpret_cast<uint32_t*>(Hl + a_lo * LD_H + colc) = lp;
                        sp2(make_float2(f2, f3), hp, lp);
                        *reinterpret_cast<uint32_t*>(Hh + a_hi * LD_H + colc) = hp;
                        *reinterpret_cast<uint32_t*>(Hl + a_hi * LD_H + colc) = lp;
                    }
                }
            }
        }
        __syncthreads();

        // ---- GEMM3: out = relu(H @ Wo + bo)  [64 x 64], K=128 (permuted-K) ----
        {
            const int rb = w & 3, cs = w >> 2;
            float c[2][4] = {};
#pragma unroll
            for (int kt = 0; kt < 8; ++kt) {
                int k0 = 16 * kt + 4 * q;
                uint32_t ah[4], al[4];
                uint2 h0 = *reinterpret_cast<const uint2*>(Hh + (rb * 16 + g) * LD_H + k0);
                uint2 h1 = *reinterpret_cast<const uint2*>(Hh + (rb * 16 + g + 8) * LD_H + k0);
                uint2 l0 = *reinterpret_cast<const uint2*>(Hl + (rb * 16 + g) * LD_H + k0);
                uint2 l1 = *reinterpret_cast<const uint2*>(Hl + (rb * 16 + g + 8) * LD_H + k0);
                ah[0] = h0.x; ah[1] = h1.x; ah[2] = h0.y; ah[3] = h1.y;
                al[0] = l0.x; al[1] = l1.x; al[2] = l0.y; al[3] = l1.y;
#pragma unroll
                for (int nt = 0; nt < 2; ++nt) {
                    uint2 B = fWO[((cs * 2 + nt) * 8 + kt) * 32 + lane];
                    mma_f16(c[nt], ah, B.x, B.y);
                    mma_f16(c[nt], al, B.x, B.y);
                }
            }
            int rlo = base + rb * 16 + g;
            int rhi = rlo + 8;
#pragma unroll
            for (int nt = 0; nt < 2; ++nt) {
                int colc = cs * 16 + nt * 8 + 2 * q;
                float2 bov = *reinterpret_cast<const float2*>(sbo + colc);
                if (rlo < n) {
                    float2 v = make_float2(relu(c[nt][0] + bov.x),
                                           relu(c[nt][1] + bov.y));
                    *reinterpret_cast<float2*>(out + (size_t)rlo * 64 + colc) = v;
                }
                if (rhi < n) {
                    float2 v = make_float2(relu(c[nt][2] + bov.x),
                                           relu(c[nt][3] + bov.y));
                    *reinterpret_cast<float2*>(out + (size_t)rhi * 64 + colc) = v;
                }
            }
        }
        __syncthreads();
    }
}

extern "C" void kernel_launch(void* const* d_in, const int* in_sizes, int n_in,
                              void* d_out, int out_size)
{
    const float* agent    = (const float*)d_in[0];
    const float* neighbor = (const float*)d_in[1];
    const int*   nmask    = (const int*)d_in[2];
    const float* Wa       = (const float*)d_in[3];
    const float* ba       = (const float*)d_in[4];
    const float* Wn       = (const float*)d_in[5];
    const float* bn       = (const float*)d_in[6];
    const float* Wh       = (const float*)d_in[7];
    const float* bh       = (const float*)d_in[8];
    const float* Wo       = (const float*)d_in[9];
    const float* bo       = (const float*)d_in[10];
    float* out = (float*)d_out;

    const int n = in_sizes[0] / 64;
    const int ntiles = (n + 63) / 64;

    cudaFuncSetAttribute(gat_mma10, cudaFuncAttributeMaxDynamicSharedMemorySize,
                         SMEM_TOTAL);

    int sms = 148;
    cudaDeviceGetAttribute(&sms, cudaDevAttrMultiProcessorCount, 0);
    int grid = sms < ntiles ? sms : ntiles;
    if (grid < 1) grid = 1;

    gat_mma10<<<grid, THREADS, SMEM_TOTAL>>>(agent, neighbor, nmask,
                                             Wa, ba, Wn, bn, Wh, bh, Wo, bo,
                                             out, n, ntiles);
}

// round 15
// speedup vs baseline: 1.4249x; 1.4249x over previous
#include <cuda_runtime.h>
#include <cuda_fp16.h>
#include <cstdint>

#define THREADS 512

// ---- SMEM byte offsets ----
enum {
  O_FWA  = 0,        // GEMM1 B frags: uint4[8 pair][4 kt][32 lane]  (16 KB)
  O_FWNH = 16384,    // GEMM2 B frags: uint4[16 pair][4 kt][32 lane] (32 KB)
  O_FWO  = 49152,    // GEMM3 B frags: uint4[4 pair][8 kt][32 lane]  (16 KB)
  O_HH   = 65536,    // H hi [64][136] half
  O_HL   = 82944,
  O_AS   = 100352,   // A f32 [64][132]
  O_BA   = 134144,   // f32[128]
  O_BN   = 134656,
  O_BH   = 135168,
  O_BO   = 135680,   // f32[64]
  O_MSK  = 135936,   // f32[256]
  SMEM_TOTAL = 136960
};

#define LD_H   136
#define LD_AS  132

__device__ __forceinline__ void mma_f16(float* c, const uint32_t* a,
                                        uint32_t b0, uint32_t b1) {
    asm volatile(
        "mma.sync.aligned.m16n8k16.row.col.f32.f16.f16.f32 "
        "{%0,%1,%2,%3}, {%4,%5,%6,%7}, {%8,%9}, {%0,%1,%2,%3};\n"
        : "+f"(c[0]), "+f"(c[1]), "+f"(c[2]), "+f"(c[3])
        : "r"(a[0]), "r"(a[1]), "r"(a[2]), "r"(a[3]), "r"(b0), "r"(b1));
}

__device__ __forceinline__ void sp2(float2 v, uint32_t& h, uint32_t& l) {
    __half2 hh = __floats2half2_rn(v.x, v.y);
    __half2 ll = __floats2half2_rn(v.x - __low2float(hh), v.y - __high2float(hh));
    h = *reinterpret_cast<uint32_t*>(&hh);
    l = *reinterpret_cast<uint32_t*>(&ll);
}

__device__ __forceinline__ float relu(float x) { return fmaxf(x, 0.f); }

// round 4 weight values (k0,k0+1,k0+8,k0+9 of one n-col) -> uint2 (R13 layout)
__device__ __forceinline__ uint2 packB(float w0, float w1, float w2, float w3) {
    __half2 h01 = __floats2half2_rn(w0, w1);
    __half2 h23 = __floats2half2_rn(w2, w3);
    uint2 r;
    r.x = *reinterpret_cast<uint32_t*>(&h01);
    r.y = *reinterpret_cast<uint32_t*>(&h23);
    return r;
}

// fp16 hi/lo A-fragments for a 16-row block (rows g, g+8), K=64 — A kept EXACT
// (byte-for-byte R13 version; do not perturb)
__device__ __forceinline__ void load_afrags(const float* rl, const float* rh,
                                            int q, uint32_t ah[4][4], uint32_t al[4][4]) {
#pragma unroll
    for (int kt = 0; kt < 4; ++kt) {
        int c0 = 16 * kt + 2 * q;
        sp2(*reinterpret_cast<const float2*>(rl + c0),     ah[kt][0], al[kt][0]);
        sp2(*reinterpret_cast<const float2*>(rh + c0),     ah[kt][1], al[kt][1]);
        sp2(*reinterpret_cast<const float2*>(rl + c0 + 8), ah[kt][2], al[kt][2]);
        sp2(*reinterpret_cast<const float2*>(rh + c0 + 8), ah[kt][3], al[kt][3]);
    }
}

__global__ __launch_bounds__(THREADS, 1)
void gat_mma11(const float* __restrict__ agent,
               const float* __restrict__ neighbor,
               const int*   __restrict__ nmask,
               const float* __restrict__ Wa, const float* __restrict__ ba,
               const float* __restrict__ Wn, const float* __restrict__ bn,
               const float* __restrict__ Wh, const float* __restrict__ bh,
               const float* __restrict__ Wo, const float* __restrict__ bo,
               float* __restrict__ out, int n, int ntiles)
{
    extern __shared__ char sm[];
    uint4*  fWA  = (uint4*)(sm + O_FWA);
    uint4*  fWNH = (uint4*)(sm + O_FWNH);
    uint4*  fWO  = (uint4*)(sm + O_FWO);
    __half* Hh   = (__half*)(sm + O_HH);
    __half* Hl   = (__half*)(sm + O_HL);
    float*  A_s  = (float*)(sm + O_AS);
    float*  sba  = (float*)(sm + O_BA);
    float*  sbn  = (float*)(sm + O_BN);
    float*  sbh  = (float*)(sm + O_BH);
    float*  sbo  = (float*)(sm + O_BO);
    float*  msk  = (float*)(sm + O_MSK);

    const int tid  = threadIdx.x;
    const int lane = tid & 31;
    const int w    = tid >> 5;
    const int g    = lane >> 2;
    const int q    = lane & 3;

    // ---- once: pack rounded-fp16 weights, PAIRED n-blocks per uint4 ----
    for (int i = tid; i < 1024; i += THREADS) {          // Wa^T: 8 pair x 4 kt
        int li = i & 31, kt = (i >> 5) & 3, p = i >> 7;
        int nn0 = 16 * p + (li >> 2), k0 = kt * 16 + 2 * (li & 3);
        uint2 b0 = packB(Wa[k0 * 128 + nn0], Wa[(k0 + 1) * 128 + nn0],
                         Wa[(k0 + 8) * 128 + nn0], Wa[(k0 + 9) * 128 + nn0]);
        int nn1 = nn0 + 8;
        uint2 b1 = packB(Wa[k0 * 128 + nn1], Wa[(k0 + 1) * 128 + nn1],
                         Wa[(k0 + 8) * 128 + nn1], Wa[(k0 + 9) * 128 + nn1]);
        fWA[i] = make_uint4(b0.x, b0.y, b1.x, b1.y);
    }
    for (int i = tid; i < 2048; i += THREADS) {          // (Wn|Wh)^T: 16 pair x 4 kt
        int li = i & 31, kt = (i >> 5) & 3, p = i >> 7;
        const float* Wsrc = (p < 8) ? Wn : Wh;
        int pc = (p < 8) ? p : p - 8;
        int nn0 = 16 * pc + (li >> 2), k0 = kt * 16 + 2 * (li & 3);
        uint2 b0 = packB(Wsrc[k0 * 128 + nn0], Wsrc[(k0 + 1) * 128 + nn0],
                         Wsrc[(k0 + 8) * 128 + nn0], Wsrc[(k0 + 9) * 128 + nn0]);
        int nn1 = nn0 + 8;
        uint2 b1 = packB(Wsrc[k0 * 128 + nn1], Wsrc[(k0 + 1) * 128 + nn1],
                         Wsrc[(k0 + 8) * 128 + nn1], Wsrc[(k0 + 9) * 128 + nn1]);
        fWNH[i] = make_uint4(b0.x, b0.y, b1.x, b1.y);
    }
    for (int i = tid; i < 1024; i += THREADS) {          // Wo^T: 4 pair x 8 kt
        int li = i & 31, kt = (i >> 5) & 7, p = i >> 8;
        int nn0 = 16 * p + (li >> 2), k0 = kt * 16 + 2 * (li & 3);
        uint2 b0 = packB(Wo[k0 * 64 + nn0], Wo[(k0 + 1) * 64 + nn0],
                         Wo[(k0 + 8) * 64 + nn0], Wo[(k0 + 9) * 64 + nn0]);
        int nn1 = nn0 + 8;
        uint2 b1 = packB(Wo[k0 * 64 + nn1], Wo[(k0 + 1) * 64 + nn1],
                         Wo[(k0 + 8) * 64 + nn1], Wo[(k0 + 9) * 64 + nn1]);
        fWO[i] = make_uint4(b0.x, b0.y, b1.x, b1.y);
    }
    if (tid < 128) {
        sba[tid] = ba[tid]; sbn[tid] = bn[tid]; sbh[tid] = bh[tid];
        if (tid < 64) sbo[tid] = bo[tid];
    }
    __syncthreads();

    for (int tile = blockIdx.x; tile < ntiles; tile += gridDim.x) {
        const int base = tile * 64;

        if (tid < 256) {
            int ag = min(base + (tid >> 2), n - 1);
            msk[tid] = (float)nmask[(size_t)ag * 4 + (tid & 3)];
        }

        // ---- GEMM1: A_s = relu(X @ Wa + ba)  [64 x 128], K=64 ----
        {
            const int rb = w & 3, cs = w >> 2;
            uint32_t ah[4][4], al[4][4];
            int rlo = min(base + rb * 16 + g,     n - 1);
            int rhi = min(base + rb * 16 + g + 8, n - 1);
            load_afrags(agent + (size_t)rlo * 64, agent + (size_t)rhi * 64, q, ah, al);
#pragma unroll
            for (int pt = 0; pt < 2; ++pt) {
                float c[2][4] = {};
                const int p = cs * 2 + pt;           // pair -> nblks 2p, 2p+1
#pragma unroll
                for (int kt = 0; kt < 4; ++kt) {
                    uint4 B = fWA[(p * 4 + kt) * 32 + lane];
                    mma_f16(c[0], ah[kt], B.x, B.y);
                    mma_f16(c[0], al[kt], B.x, B.y);
                    mma_f16(c[1], ah[kt], B.z, B.w);
                    mma_f16(c[1], al[kt], B.z, B.w);
                }
#pragma unroll
                for (int u = 0; u < 2; ++u) {
                    int colc = cs * 32 + (pt * 2 + u) * 8 + 2 * q;
                    float2 bav = *reinterpret_cast<const float2*>(sba + colc);
                    float* d0 = A_s + (rb * 16 + g) * LD_AS + colc;
                    float* d1 = A_s + (rb * 16 + g + 8) * LD_AS + colc;
                    d0[0] = relu(c[u][0] + bav.x); d0[1] = relu(c[u][1] + bav.y);
                    d1[0] = relu(c[u][2] + bav.x); d1[1] = relu(c[u][3] + bav.y);
                }
            }
        }
        __syncthreads();

        // ---- GEMM2 + attention epilogue: one 16-row block per warp ----
        {
            const int blk  = w;                  // 4 agents
            const int a_lo = blk * 4 + (g >> 2);
            const int a_hi = a_lo + 2;
            int agl = min(base + a_lo, n - 1);
            int agh = min(base + a_hi, n - 1);
            uint32_t ah[4][4], al[4][4];
            load_afrags(neighbor + ((size_t)agl * 4 + (g & 3)) * 64,
                        neighbor + ((size_t)agh * 4 + (g & 3)) * 64, q, ah, al);

            const float mk_lo = msk[blk * 16 + g];
            const float mk_hi = msk[blk * 16 + g + 8];
            const float* arow_lo = A_s + a_lo * LD_AS;
            const float* arow_hi = A_s + a_hi * LD_AS;

#pragma unroll 1
            for (int h = 0; h < 4; ++h) {
                float c[4][4] = {};
                // --- nr GEMM: pairs 2h, 2h+1 ---
#pragma unroll
                for (int kt = 0; kt < 4; ++kt) {
#pragma unroll
                    for (int pt = 0; pt < 2; ++pt) {
                        uint4 B = fWNH[((2 * h + pt) * 4 + kt) * 32 + lane];
                        mma_f16(c[2 * pt + 0], ah[kt], B.x, B.y);
                        mma_f16(c[2 * pt + 0], al[kt], B.x, B.y);
                        mma_f16(c[2 * pt + 1], ah[kt], B.z, B.w);
                        mma_f16(c[2 * pt + 1], al[kt], B.z, B.w);
                    }
                }
                // --- attention logits ---
                float p_lo = 0.f, p_hi = 0.f;
#pragma unroll
                for (int nt = 0; nt < 4; ++nt) {
                    int colc = 32 * h + 8 * nt + 2 * q;
                    float2 bnv = *reinterpret_cast<const float2*>(sbn + colc);
                    float e0 = relu(c[nt][0] + bnv.x), e1 = relu(c[nt][1] + bnv.y);
                    float e2 = relu(c[nt][2] + bnv.x), e3 = relu(c[nt][3] + bnv.y);
                    float2 avl = *reinterpret_cast<const float2*>(arow_lo + colc);
                    float2 avh = *reinterpret_cast<const float2*>(arow_hi + colc);
                    p_lo = fmaf(e0, avl.x, fmaf(e1, avl.y, p_lo));
                    p_hi = fmaf(e2, avh.x, fmaf(e3, avh.y, p_hi));
                }
                p_lo += __shfl_xor_sync(0xffffffffu, p_lo, 1);
                p_lo += __shfl_xor_sync(0xffffffffu, p_lo, 2);
                p_hi += __shfl_xor_sync(0xffffffffu, p_hi, 1);
                p_hi += __shfl_xor_sync(0xffffffffu, p_hi, 2);
                // --- softmax over the agent's 4 neighbor rows ---
                float lg_lo = fmaf(mk_lo, -1e8f, p_lo);
                float lg_hi = fmaf(mk_hi, -1e8f, p_hi);
                float m_lo = lg_lo, m_hi = lg_hi;
                m_lo = fmaxf(m_lo, __shfl_xor_sync(0xffffffffu, m_lo, 4));
                m_lo = fmaxf(m_lo, __shfl_xor_sync(0xffffffffu, m_lo, 8));
                m_hi = fmaxf(m_hi, __shfl_xor_sync(0xffffffffu, m_hi, 4));
                m_hi = fmaxf(m_hi, __shfl_xor_sync(0xffffffffu, m_hi, 8));
                float e_lo = __expf(lg_lo - m_lo), e_hi = __expf(lg_hi - m_hi);
                float s_lo = e_lo, s_hi = e_hi;
                s_lo += __shfl_xor_sync(0xffffffffu, s_lo, 4);
                s_lo += __shfl_xor_sync(0xffffffffu, s_lo, 8);
                s_hi += __shfl_xor_sync(0xffffffffu, s_hi, 4);
                s_hi += __shfl_xor_sync(0xffffffffu, s_hi, 8);
                float sc_lo = (1.f - mk_lo) * e_lo * 0.25f / s_lo;
                float sc_hi = (1.f - mk_hi) * e_hi * 0.25f / s_hi;

                // --- nh GEMM: pairs 8+2h, 8+2h+1 ---
#pragma unroll
                for (int nt = 0; nt < 4; ++nt)
                    c[nt][0] = c[nt][1] = c[nt][2] = c[nt][3] = 0.f;
#pragma unroll
                for (int kt = 0; kt < 4; ++kt) {
#pragma unroll
                    for (int pt = 0; pt < 2; ++pt) {
                        uint4 B = fWNH[((8 + 2 * h + pt) * 4 + kt) * 32 + lane];
                        mma_f16(c[2 * pt + 0], ah[kt], B.x, B.y);
                        mma_f16(c[2 * pt + 0], al[kt], B.x, B.y);
                        mma_f16(c[2 * pt + 1], ah[kt], B.z, B.w);
                        mma_f16(c[2 * pt + 1], al[kt], B.z, B.w);
                    }
                }
                // --- weighted mean -> H ---
#pragma unroll
                for (int nt = 0; nt < 4; ++nt) {
                    int colc = 32 * h + 8 * nt + 2 * q;
                    float2 bhv = *reinterpret_cast<const float2*>(sbh + colc);
                    float f0 = relu(c[nt][0] + bhv.x) * sc_lo;
                    float f1 = relu(c[nt][1] + bhv.y) * sc_lo;
                    float f2 = relu(c[nt][2] + bhv.x) * sc_hi;
                    float f3 = relu(c[nt][3] + bhv.y) * sc_hi;
                    f0 += __shfl_xor_sync(0xffffffffu, f0, 4);
                    f0 += __shfl_xor_sync(0xffffffffu, f0, 8);
                    f1 += __shfl_xor_sync(0xffffffffu, f1, 4);
                    f1 += __shfl_xor_sync(0xffffffffu, f1, 8);
                    f2 += __shfl_xor_sync(0xffffffffu, f2, 4);
                    f2 += __shfl_xor_sync(0xffffffffu, f2, 8);
                    f3 += __shfl_xor_sync(0xffffffffu, f3, 4);
                    f3 += __shfl_xor_sync(0xffffffffu, f3, 8);
                    if ((g & 3) == 0) {
                        uint32_t hp, lp;
                        sp2(make_float2(f0, f1), hp, lp);
                        *reinterpret_cast<uint32_t*>(Hh + a_lo * LD_H + colc) = hp;
                        *reinterpret_cast<uint32_t*>(Hl + a_lo * LD_H + colc) = lp;
                        sp2(make_float2(f2, f3), hp, lp);
                        *reinterpret_cast<uint32_t*>(Hh + a_hi * LD_H + colc) = hp;
                        *reinterpret_cast<uint32_t*>(Hl + a_hi * LD_H + colc) = lp;
                    }
                }
            }
        }
        __syncthreads();

        // ---- GEMM3: out = relu(H @ Wo + bo)  [64 x 64], K=128 ----
        {
            const int rb = w & 3, cs = w >> 2;
            float c[2][4] = {};
#pragma unroll
            for (int kt = 0; kt < 8; ++kt) {
                int k0 = 16 * kt + 2 * q;
                uint32_t ah[4], al[4];
                const __half* hl = Hh + (rb * 16 + g) * LD_H + k0;
                const __half* hu = Hh + (rb * 16 + g + 8) * LD_H + k0;
                const __half* ll = Hl + (rb * 16 + g) * LD_H + k0;
                const __half* lu = Hl + (rb * 16 + g + 8) * LD_H + k0;
                ah[0] = *reinterpret_cast<const uint32_t*>(hl);
                ah[1] = *reinterpret_cast<const uint32_t*>(hu);
                ah[2] = *reinterpret_cast<const uint32_t*>(hl + 8);
                ah[3] = *reinterpret_cast<const uint32_t*>(hu + 8);
                al[0] = *reinterpret_cast<const uint32_t*>(ll);
                al[1] = *reinterpret_cast<const uint32_t*>(lu);
                al[2] = *reinterpret_cast<const uint32_t*>(ll + 8);
                al[3] = *reinterpret_cast<const uint32_t*>(lu + 8);
                uint4 B = fWO[(cs * 8 + kt) * 32 + lane];
                mma_f16(c[0], ah, B.x, B.y);
                mma_f16(c[0], al, B.x, B.y);
                mma_f16(c[1], ah, B.z, B.w);
                mma_f16(c[1], al, B.z, B.w);
            }
            int rlo = base + rb * 16 + g;
            int rhi = rlo + 8;
#pragma unroll
            for (int nt = 0; nt < 2; ++nt) {
                int colc = cs * 16 + nt * 8 + 2 * q;
                float2 bov = *reinterpret_cast<const float2*>(sbo + colc);
                if (rlo < n) {
                    float2 v = make_float2(relu(c[nt][0] + bov.x),
                                           relu(c[nt][1] + bov.y));
                    *reinterpret_cast<float2*>(out + (size_t)rlo * 64 + colc) = v;
                }
                if (rhi < n) {
                    float2 v = make_float2(relu(c[nt][2] + bov.x),
                                           relu(c[nt][3] + bov.y));
                    *reinterpret_cast<float2*>(out + (size_t)rhi * 64 + colc) = v;
                }
            }
        }
        __syncthreads();
    }
}

extern "C" void kernel_launch(void* const* d_in, const int* in_sizes, int n_in,
                              void* d_out, int out_size)
{
    const float* agent    = (const float*)d_in[0];
    const float* neighbor = (const float*)d_in[1];
    const int*   nmask    = (const int*)d_in[2];
    const float* Wa       = (const float*)d_in[3];
    const float* ba       = (const float*)d_in[4];
    const float* Wn       = (const float*)d_in[5];
    const float* bn       = (const float*)d_in[6];
    const float* Wh       = (const float*)d_in[7];
    const float* bh       = (const float*)d_in[8];
    const float* Wo       = (const float*)d_in[9];
    const float* bo       = (const float*)d_in[10];
    float* out = (float*)d_out;

    const int n = in_sizes[0] / 64;
    const int ntiles = (n + 63) / 64;

    cudaFuncSetAttribute(gat_mma11, cudaFuncAttributeMaxDynamicSharedMemorySize,
                         SMEM_TOTAL);

    int sms = 148;
    cudaDeviceGetAttribute(&sms, cudaDevAttrMultiProcessorCount, 0);
    int grid = sms < ntiles ? sms : ntiles;
    if (grid < 1) grid = 1;

    gat_mma11<<<grid, THREADS, SMEM_TOTAL>>>(agent, neighbor, nmask,
                                             Wa, ba, Wn, bn, Wh, bh, Wo, bo,
                                             out, n, ntiles);
}

// round 16
// speedup vs baseline: 1.6500x; 1.1580x over previous
#include <cuda_runtime.h>
#include <cuda_fp16.h>
#include <cstdint>

#define THREADS 512

// ---- SMEM byte offsets ----
enum {
  O_FWA  = 0,        // GEMM1 B frags: uint2[16 nblk][4 kt][32 lane] (16 KB)
  O_FWNH = 16384,    // GEMM2 B frags: uint2[32 nblk][4 kt][32 lane] (32 KB)
  O_FWO  = 49152,    // GEMM3 B frags: uint2[8 nblk][8 kt][32 lane]  (16 KB)
  O_HH   = 65536,    // H hi [64][136] half
  O_HL   = 82944,
  O_AS   = 100352,   // A f32 [64][132]
  O_BA   = 134144,   // f32[128]
  O_BN   = 134656,
  O_BH   = 135168,
  O_BO   = 135680,   // f32[64]
  O_MSK  = 135936,   // f32[256]
  SMEM_TOTAL = 136960
};

#define LD_H   136
#define LD_AS  132

__device__ __forceinline__ void mma_f16(float* c, const uint32_t* a,
                                        uint32_t b0, uint32_t b1) {
    asm volatile(
        "mma.sync.aligned.m16n8k16.row.col.f32.f16.f16.f32 "
        "{%0,%1,%2,%3}, {%4,%5,%6,%7}, {%8,%9}, {%0,%1,%2,%3};\n"
        : "+f"(c[0]), "+f"(c[1]), "+f"(c[2]), "+f"(c[3])
        : "r"(a[0]), "r"(a[1]), "r"(a[2]), "r"(a[3]), "r"(b0), "r"(b1));
}

__device__ __forceinline__ void sp2(float2 v, uint32_t& h, uint32_t& l) {
    __half2 hh = __floats2half2_rn(v.x, v.y);
    __half2 ll = __floats2half2_rn(v.x - __low2float(hh), v.y - __high2float(hh));
    h = *reinterpret_cast<uint32_t*>(&hh);
    l = *reinterpret_cast<uint32_t*>(&ll);
}

__device__ __forceinline__ uint32_t sph(float2 v) {
    __half2 hh = __floats2half2_rn(v.x, v.y);
    return *reinterpret_cast<uint32_t*>(&hh);
}

__device__ __forceinline__ float relu(float x) { return fmaxf(x, 0.f); }

// round 4 weight values to fp16 (hi only) packed as uint2
__device__ __forceinline__ uint2 packB(float w0, float w1, float w2, float w3) {
    __half2 h01 = __floats2half2_rn(w0, w1);
    __half2 h23 = __floats2half2_rn(w2, w3);
    uint2 r;
    r.x = *reinterpret_cast<uint32_t*>(&h01);
    r.y = *reinterpret_cast<uint32_t*>(&h23);
    return r;
}

// fp16 hi/lo A-fragments for a 16-row block (rows g, g+8), K=64 — A kept EXACT
// (byte-for-byte R13 version; used by GEMM1)
__device__ __forceinline__ void load_afrags(const float* rl, const float* rh,
                                            int q, uint32_t ah[4][4], uint32_t al[4][4]) {
#pragma unroll
    for (int kt = 0; kt < 4; ++kt) {
        int c0 = 16 * kt + 2 * q;
        sp2(*reinterpret_cast<const float2*>(rl + c0),     ah[kt][0], al[kt][0]);
        sp2(*reinterpret_cast<const float2*>(rh + c0),     ah[kt][1], al[kt][1]);
        sp2(*reinterpret_cast<const float2*>(rl + c0 + 8), ah[kt][2], al[kt][2]);
        sp2(*reinterpret_cast<const float2*>(rh + c0 + 8), ah[kt][3], al[kt][3]);
    }
}

// hi-only A-fragments (GEMM2: neighbor activations rounded to fp16)
__device__ __forceinline__ void load_afrags_hi(const float* rl, const float* rh,
                                               int q, uint32_t ah[4][4]) {
#pragma unroll
    for (int kt = 0; kt < 4; ++kt) {
        int c0 = 16 * kt + 2 * q;
        ah[kt][0] = sph(*reinterpret_cast<const float2*>(rl + c0));
        ah[kt][1] = sph(*reinterpret_cast<const float2*>(rh + c0));
        ah[kt][2] = sph(*reinterpret_cast<const float2*>(rl + c0 + 8));
        ah[kt][3] = sph(*reinterpret_cast<const float2*>(rh + c0 + 8));
    }
}

__global__ __launch_bounds__(THREADS, 1)
void gat_mma12(const float* __restrict__ agent,
               const float* __restrict__ neighbor,
               const int*   __restrict__ nmask,
               const float* __restrict__ Wa, const float* __restrict__ ba,
               const float* __restrict__ Wn, const float* __restrict__ bn,
               const float* __restrict__ Wh, const float* __restrict__ bh,
               const float* __restrict__ Wo, const float* __restrict__ bo,
               float* __restrict__ out, int n, int ntiles)
{
    extern __shared__ char sm[];
    uint2*  fWA  = (uint2*)(sm + O_FWA);
    uint2*  fWNH = (uint2*)(sm + O_FWNH);
    uint2*  fWO  = (uint2*)(sm + O_FWO);
    __half* Hh   = (__half*)(sm + O_HH);
    __half* Hl   = (__half*)(sm + O_HL);
    float*  A_s  = (float*)(sm + O_AS);
    float*  sba  = (float*)(sm + O_BA);
    float*  sbn  = (float*)(sm + O_BN);
    float*  sbh  = (float*)(sm + O_BH);
    float*  sbo  = (float*)(sm + O_BO);
    float*  msk  = (float*)(sm + O_MSK);

    const int tid  = threadIdx.x;
    const int lane = tid & 31;
    const int w    = tid >> 5;
    const int g    = lane >> 2;
    const int q    = lane & 3;

    // ---- once: pack rounded-fp16 weights into fragment-ready SMEM ----
    for (int i = tid; i < 2048; i += THREADS) {          // Wa^T: 16 nblk x 4 kt
        int li = i & 31, kt = (i >> 5) & 3, nb = i >> 7;
        int nn = nb * 8 + (li >> 2), k0 = kt * 16 + 2 * (li & 3);
        fWA[i] = packB(Wa[k0 * 128 + nn], Wa[(k0 + 1) * 128 + nn],
                       Wa[(k0 + 8) * 128 + nn], Wa[(k0 + 9) * 128 + nn]);
    }
    for (int i = tid; i < 4096; i += THREADS) {          // (Wn|Wh)^T: 32 nblk x 4 kt
        int li = i & 31, kt = (i >> 5) & 3, nb = i >> 7;
        int nn = nb * 8 + (li >> 2), k0 = kt * 16 + 2 * (li & 3);
        const float* Wsrc = (nn < 128) ? Wn : Wh;
        int nc = (nn < 128) ? nn : nn - 128;
        fWNH[i] = packB(Wsrc[k0 * 128 + nc], Wsrc[(k0 + 1) * 128 + nc],
                        Wsrc[(k0 + 8) * 128 + nc], Wsrc[(k0 + 9) * 128 + nc]);
    }
    for (int i = tid; i < 2048; i += THREADS) {          // Wo^T: 8 nblk x 8 kt
        int li = i & 31, kt = (i >> 5) & 7, nb = i >> 8;
        int nn = nb * 8 + (li >> 2), k0 = kt * 16 + 2 * (li & 3);
        fWO[i] = packB(Wo[k0 * 64 + nn], Wo[(k0 + 1) * 64 + nn],
                       Wo[(k0 + 8) * 64 + nn], Wo[(k0 + 9) * 64 + nn]);
    }
    if (tid < 128) {
        sba[tid] = ba[tid]; sbn[tid] = bn[tid]; sbh[tid] = bh[tid];
        if (tid < 64) sbo[tid] = bo[tid];
    }
    __syncthreads();

    for (int tile = blockIdx.x; tile < ntiles; tile += gridDim.x) {
        const int base = tile * 64;

        if (tid < 256) {
            int ag = min(base + (tid >> 2), n - 1);
            msk[tid] = (float)nmask[(size_t)ag * 4 + (tid & 3)];
        }

        // ---- GEMM1: A_s = relu(X @ Wa + ba)  [64 x 128], K=64 (exact-A) ----
        {
            const int rb = w & 3, cs = w >> 2;
            uint32_t ah[4][4], al[4][4];
            int rlo = min(base + rb * 16 + g,     n - 1);
            int rhi = min(base + rb * 16 + g + 8, n - 1);
            load_afrags(agent + (size_t)rlo * 64, agent + (size_t)rhi * 64, q, ah, al);
#pragma unroll
            for (int nt = 0; nt < 4; ++nt) {
                float c[4] = {0.f, 0.f, 0.f, 0.f};
                const int nb = cs * 4 + nt;
#pragma unroll
                for (int kt = 0; kt < 4; ++kt) {
                    uint2 B = fWA[(nb * 4 + kt) * 32 + lane];
                    mma_f16(c, ah[kt], B.x, B.y);
                    mma_f16(c, al[kt], B.x, B.y);
                }
                int colc = cs * 32 + nt * 8 + 2 * q;
                float2 bav = *reinterpret_cast<const float2*>(sba + colc);
                float* d0 = A_s + (rb * 16 + g) * LD_AS + colc;
                float* d1 = A_s + (rb * 16 + g + 8) * LD_AS + colc;
                d0[0] = relu(c[0] + bav.x); d0[1] = relu(c[1] + bav.y);
                d1[0] = relu(c[2] + bav.x); d1[1] = relu(c[3] + bav.y);
            }
        }
        __syncthreads();

        // ---- GEMM2 (hi-only A) + attention epilogue: one 16-row block per warp ----
        {
            const int blk  = w;                  // 4 agents
            const int a_lo = blk * 4 + (g >> 2);
            const int a_hi = a_lo + 2;
            int agl = min(base + a_lo, n - 1);
            int agh = min(base + a_hi, n - 1);
            uint32_t ah[4][4];
            load_afrags_hi(neighbor + ((size_t)agl * 4 + (g & 3)) * 64,
                           neighbor + ((size_t)agh * 4 + (g & 3)) * 64, q, ah);

            const float mk_lo = msk[blk * 16 + g];
            const float mk_hi = msk[blk * 16 + g + 8];
            const float* arow_lo = A_s + a_lo * LD_AS;
            const float* arow_hi = A_s + a_hi * LD_AS;

#pragma unroll 1
            for (int h = 0; h < 4; ++h) {
                float c[4][4] = {};
                // --- nr GEMM (nblk = 4h+nt) ---
#pragma unroll
                for (int kt = 0; kt < 4; ++kt) {
#pragma unroll
                    for (int nt = 0; nt < 4; ++nt) {
                        uint2 B = fWNH[((4 * h + nt) * 4 + kt) * 32 + lane];
                        mma_f16(c[nt], ah[kt], B.x, B.y);
                    }
                }
                // --- attention logits ---
                float p_lo = 0.f, p_hi = 0.f;
#pragma unroll
                for (int nt = 0; nt < 4; ++nt) {
                    int colc = 32 * h + 8 * nt + 2 * q;
                    float2 bnv = *reinterpret_cast<const float2*>(sbn + colc);
                    float e0 = relu(c[nt][0] + bnv.x), e1 = relu(c[nt][1] + bnv.y);
                    float e2 = relu(c[nt][2] + bnv.x), e3 = relu(c[nt][3] + bnv.y);
                    float2 avl = *reinterpret_cast<const float2*>(arow_lo + colc);
                    float2 avh = *reinterpret_cast<const float2*>(arow_hi + colc);
                    p_lo = fmaf(e0, avl.x, fmaf(e1, avl.y, p_lo));
                    p_hi = fmaf(e2, avh.x, fmaf(e3, avh.y, p_hi));
                }
                p_lo += __shfl_xor_sync(0xffffffffu, p_lo, 1);
                p_lo += __shfl_xor_sync(0xffffffffu, p_lo, 2);
                p_hi += __shfl_xor_sync(0xffffffffu, p_hi, 1);
                p_hi += __shfl_xor_sync(0xffffffffu, p_hi, 2);
                // --- softmax over the agent's 4 neighbor rows ---
                float lg_lo = fmaf(mk_lo, -1e8f, p_lo);
                float lg_hi = fmaf(mk_hi, -1e8f, p_hi);
                float m_lo = lg_lo, m_hi = lg_hi;
                m_lo = fmaxf(m_lo, __shfl_xor_sync(0xffffffffu, m_lo, 4));
                m_lo = fmaxf(m_lo, __shfl_xor_sync(0xffffffffu, m_lo, 8));
                m_hi = fmaxf(m_hi, __shfl_xor_sync(0xffffffffu, m_hi, 4));
                m_hi = fmaxf(m_hi, __shfl_xor_sync(0xffffffffu, m_hi, 8));
                float e_lo = __expf(lg_lo - m_lo), e_hi = __expf(lg_hi - m_hi);
                float s_lo = e_lo, s_hi = e_hi;
                s_lo += __shfl_xor_sync(0xffffffffu, s_lo, 4);
                s_lo += __shfl_xor_sync(0xffffffffu, s_lo, 8);
                s_hi += __shfl_xor_sync(0xffffffffu, s_hi, 4);
                s_hi += __shfl_xor_sync(0xffffffffu, s_hi, 8);
                float sc_lo = (1.f - mk_lo) * e_lo * 0.25f / s_lo;
                float sc_hi = (1.f - mk_hi) * e_hi * 0.25f / s_hi;

                // --- nh GEMM (nblk = 16+4h+nt) ---
#pragma unroll
                for (int nt = 0; nt < 4; ++nt)
                    c[nt][0] = c[nt][1] = c[nt][2] = c[nt][3] = 0.f;
#pragma unroll
                for (int kt = 0; kt < 4; ++kt) {
#pragma unroll
                    for (int nt = 0; nt < 4; ++nt) {
                        uint2 B = fWNH[((16 + 4 * h + nt) * 4 + kt) * 32 + lane];
                        mma_f16(c[nt], ah[kt], B.x, B.y);
                    }
                }
                // --- weighted mean -> H ---
#pragma unroll
                for (int nt = 0; nt < 4; ++nt) {
                    int colc = 32 * h + 8 * nt + 2 * q;
                    float2 bhv = *reinterpret_cast<const float2*>(sbh + colc);
                    float f0 = relu(c[nt][0] + bhv.x) * sc_lo;
                    float f1 = relu(c[nt][1] + bhv.y) * sc_lo;
                    float f2 = relu(c[nt][2] + bhv.x) * sc_hi;
                    float f3 = relu(c[nt][3] + bhv.y) * sc_hi;
                    f0 += __shfl_xor_sync(0xffffffffu, f0, 4);
                    f0 += __shfl_xor_sync(0xffffffffu, f0, 8);
                    f1 += __shfl_xor_sync(0xffffffffu, f1, 4);
                    f1 += __shfl_xor_sync(0xffffffffu, f1, 8);
                    f2 += __shfl_xor_sync(0xffffffffu, f2, 4);
                    f2 += __shfl_xor_sync(0xffffffffu, f2, 8);
                    f3 += __shfl_xor_sync(0xffffffffu, f3, 4);
                    f3 += __shfl_xor_sync(0xffffffffu, f3, 8);
                    if ((g & 3) == 0) {
                        uint32_t hp, lp;
                        sp2(make_float2(f0, f1), hp, lp);
                        *reinterpret_cast<uint32_t*>(Hh + a_lo * LD_H + colc) = hp;
                        *reinterpret_cast<uint32_t*>(Hl + a_lo * LD_H + colc) = lp;
                        sp2(make_float2(f2, f3), hp, lp);
                        *reinterpret_cast<uint32_t*>(Hh + a_hi * LD_H + colc) = hp;
                        *reinterpret_cast<uint32_t*>(Hl + a_hi * LD_H + colc) = lp;
                    }
                }
            }
        }
        __syncthreads();

        // ---- GEMM3: out = relu(H @ Wo + bo)  [64 x 64], K=128 (exact-A) ----
        {
            const int rb = w & 3, cs = w >> 2;
            float c[2][4] = {};
#pragma unroll
            for (int kt = 0; kt < 8; ++kt) {
                int k0 = 16 * kt + 2 * q;
                uint32_t ah[4], al[4];
                const __half* hl = Hh + (rb * 16 + g) * LD_H + k0;
                const __half* hu = Hh + (rb * 16 + g + 8) * LD_H + k0;
                const __half* ll = Hl + (rb * 16 + g) * LD_H + k0;
                const __half* lu = Hl + (rb * 16 + g + 8) * LD_H + k0;
                ah[0] = *reinterpret_cast<const uint32_t*>(hl);
                ah[1] = *reinterpret_cast<const uint32_t*>(hu);
                ah[2] = *reinterpret_cast<const uint32_t*>(hl + 8);
                ah[3] = *reinterpret_cast<const uint32_t*>(hu + 8);
                al[0] = *reinterpret_cast<const uint32_t*>(ll);
                al[1] = *reinterpret_cast<const uint32_t*>(lu);
                al[2] = *reinterpret_cast<const uint32_t*>(ll + 8);
                al[3] = *reinterpret_cast<const uint32_t*>(lu + 8);
#pragma unroll
                for (int nt = 0; nt < 2; ++nt) {
                    uint2 B = fWO[((cs * 2 + nt) * 8 + kt) * 32 + lane];
                    mma_f16(c[nt], ah, B.x, B.y);
                    mma_f16(c[nt], al, B.x, B.y);
                }
            }
            int rlo = base + rb * 16 + g;
            int rhi = rlo + 8;
#pragma unroll
            for (int nt = 0; nt < 2; ++nt) {
                int colc = cs * 16 + nt * 8 + 2 * q;
                float2 bov = *reinterpret_cast<const float2*>(sbo + colc);
                if (rlo < n) {
                    float2 v = make_float2(relu(c[nt][0] + bov.x),
                                           relu(c[nt][1] + bov.y));
                    *reinterpret_cast<float2*>(out + (size_t)rlo * 64 + colc) = v;
                }
                if (rhi < n) {
                    float2 v = make_float2(relu(c[nt][2] + bov.x),
                                           relu(c[nt][3] + bov.y));
                    *reinterpret_cast<float2*>(out + (size_t)rhi * 64 + colc) = v;
                }
            }
        }
        __syncthreads();
    }
}

extern "C" void kernel_launch(void* const* d_in, const int* in_sizes, int n_in,
                              void* d_out, int out_size)
{
    const float* agent    = (const float*)d_in[0];
    const float* neighbor = (const float*)d_in[1];
    const int*   nmask    = (const int*)d_in[2];
    const float* Wa       = (const float*)d_in[3];
    const float* ba       = (const float*)d_in[4];
    const float* Wn       = (const float*)d_in[5];
    const float* bn       = (const float*)d_in[6];
    const float* Wh       = (const float*)d_in[7];
    const float* bh       = (const float*)d_in[8];
    const float* Wo       = (const float*)d_in[9];
    const float* bo       = (const float*)d_in[10];
    float* out = (float*)d_out;

    const int n = in_sizes[0] / 64;
    const int ntiles = (n + 63) / 64;

    cudaFuncSetAttribute(gat_mma12, cudaFuncAttributeMaxDynamicSharedMemorySize,
                         SMEM_TOTAL);

    int sms = 148;
    cudaDeviceGetAttribute(&sms, cudaDevAttrMultiProcessorCount, 0);
    int grid = sms < ntiles ? sms : ntiles;
    if (grid < 1) grid = 1;

    gat_mma12<<<grid, THREADS, SMEM_TOTAL>>>(agent, neighbor, nmask,
                                             Wa, ba, Wn, bn, Wh, bh, Wo, bo,
                                             out, n, ntiles);
}